// round 5
// baseline (speedup 1.0000x reference)
#include <cuda_runtime.h>
#include <math.h>

#define S 1024
#define D 1024
#define H 16
#define HD 64
#define NL 6
#define DFF 4096
#define EPS 1.1920929e-07f

// ---------------- scratch (static device globals; no allocations) ----------------
__device__ float g_x [S*D];
__device__ float g_x0[S*D];
__device__ float g_xl[S*D];
__device__ float g_xn[S*D];
__device__ float g_q [S*D];
__device__ float g_k [S*D];
__device__ float g_v [S*D];
__device__ float g_v1[S*D];
__device__ float g_y [S*D];
__device__ float g_h [S*DFF];
__device__ unsigned g_mask[S][S/32];
__device__ int g_cpad[S+1];

// ---------------- mask precompute ----------------
__global__ void prefix_kernel(const int* __restrict__ levels) {
    if (blockIdx.x == 0 && threadIdx.x == 0) {
        int c = 0;
        g_cpad[0] = 0;
        for (int i = 0; i < S; i++) { c += (levels[i] == 0); g_cpad[i+1] = c; }
    }
}

__global__ void mask_kernel(const int* __restrict__ levels, const int* __restrict__ sidx) {
    int q = blockIdx.x;
    int w = threadIdx.x;          // word index, 32 words per row
    int sq = sidx[q];
    int cq = g_cpad[q];           // # level-0 tokens strictly before q
    unsigned bits = 0u;
    #pragma unroll
    for (int j = 0; j < 32; j++) {
        int k = w * 32 + j;
        bool ok = (k <= q) && (sidx[k] == sq);
        if (ok && (levels[k] == 0) && (cq - g_cpad[k+1] > 0)) ok = false;
        if (ok) bits |= (1u << j);
    }
    g_mask[q][w] = bits;
}

// ---------------- rms over last dim (D=1024), one block per row ----------------
__global__ __launch_bounds__(256) void rms_kernel(const float* __restrict__ in,
                                                  float* __restrict__ out) {
    __shared__ float sred[8];
    int row = blockIdx.x;
    const float4* ip = (const float4*)(in + (size_t)row * D);
    float4* op = (float4*)(out + (size_t)row * D);
    float4 a = ip[threadIdx.x];
    float s = a.x*a.x + a.y*a.y + a.z*a.z + a.w*a.w;
    #pragma unroll
    for (int o = 16; o > 0; o >>= 1) s += __shfl_xor_sync(0xffffffffu, s, o);
    if ((threadIdx.x & 31) == 0) sred[threadIdx.x >> 5] = s;
    __syncthreads();
    if (threadIdx.x == 0) {
        float t = 0.f;
        #pragma unroll
        for (int i = 0; i < 8; i++) t += sred[i];
        sred[0] = t;
    }
    __syncthreads();
    float r = rsqrtf(sred[0] * (1.0f / (float)D) + EPS);
    a.x *= r; a.y *= r; a.z *= r; a.w *= r;
    op[threadIdx.x] = a;
}

// ---------------- elementwise ----------------
__global__ void copy_x0_kernel() {
    int i = blockIdx.x * 256 + threadIdx.x;
    ((float4*)g_x0)[i] = ((const float4*)g_x)[i];
}

__global__ void lerp_kernel(const float* __restrict__ lambdas, int layer) {
    float l0 = lambdas[layer*2 + 0];
    float l1 = lambdas[layer*2 + 1];
    int i = blockIdx.x * 256 + threadIdx.x;
    float4 a = ((const float4*)g_x )[i];
    float4 b = ((const float4*)g_x0)[i];
    float4 o;
    o.x = l0*a.x + l1*b.x; o.y = l0*a.y + l1*b.y;
    o.z = l0*a.z + l1*b.z; o.w = l0*a.w + l1*b.w;
    ((float4*)g_xl)[i] = o;
}

__global__ void vmix_kernel(const float* __restrict__ lamb, int layer) {
    int i = blockIdx.x * 256 + threadIdx.x;
    if (layer == 0) {
        ((float4*)g_v1)[i] = ((const float4*)g_v)[i];
        // v = (1-l)*v + l*v1 == v  (no-op at layer 0)
    } else {
        float l = lamb[layer];
        float4 v = ((const float4*)g_v )[i];
        float4 u = ((const float4*)g_v1)[i];
        float4 o;
        o.x = (1.f-l)*v.x + l*u.x; o.y = (1.f-l)*v.y + l*u.y;
        o.z = (1.f-l)*v.z + l*u.z; o.w = (1.f-l)*v.w + l*u.w;
        ((float4*)g_v)[i] = o;
    }
}

// ---------------- per-head QK rms-norm + rope ----------------
// grid: S blocks, block (32,16): warp per head, lane j handles dims j and j+32
__global__ __launch_bounds__(512) void qkrope_kernel() {
    int t = blockIdx.x;
    int h = threadIdx.y;
    int j = threadIdx.x;
    float inv = powf(10000.f, -(float)j / 32.f);
    float fr = (float)t * inv;
    float c = cosf(fr), sn = sinf(fr);
    #pragma unroll
    for (int which = 0; which < 2; which++) {
        float* p = (which ? g_k : g_q) + (size_t)t * D + h * HD;
        float a = p[j];
        float b = p[j + 32];
        float ss = a*a + b*b;
        #pragma unroll
        for (int o = 16; o > 0; o >>= 1) ss += __shfl_xor_sync(0xffffffffu, ss, o);
        float r = rsqrtf(ss * (1.0f/64.0f) + EPS);
        a *= r; b *= r;
        p[j]      =  a*c + b*sn;
        p[j + 32] = -a*sn + b*c;
    }
}

// ---------------- tiled fp32 GEMM: C[M,N] = op( A[M,K] * B[N,K]^T ) ----------------
// mode 0: C = acc ; mode 1: C = Res + acc ; mode 2: C = relu(acc)^2
#define BM 128
#define BN 64
#define BK 16

__global__ __launch_bounds__(256) void gemm_kernel(
    const float* __restrict__ A, const float* __restrict__ B,
    const float* __restrict__ Res, float* __restrict__ C,
    int M, int N, int K, int mode)
{
    __shared__ float As[BK][BM];
    __shared__ float Bs[BK][BN];

    int tid = threadIdx.x;
    int m0 = blockIdx.y * BM;
    int n0 = blockIdx.x * BN;
    int tx = tid & 15;   // col group: 16 groups of 4 cols
    int ty = tid >> 4;   // row group: 16 groups of 8 rows

    float acc[8][4];
    #pragma unroll
    for (int i = 0; i < 8; i++)
        #pragma unroll
        for (int j = 0; j < 4; j++) acc[i][j] = 0.f;

    int ar  = tid >> 1;         // A row within tile (0..127)
    int akq = (tid & 1) * 2;    // which pair of float4s in the 16-wide k strip
    int br  = tid >> 2;         // B row within tile (0..63)
    int bkq = tid & 3;

    const float* Arow = A + (size_t)(m0 + ar) * K;
    const float* Brow = B + (size_t)(n0 + br) * K;

    for (int k0 = 0; k0 < K; k0 += BK) {
        float4 a0 = ((const float4*)(Arow + k0))[akq];
        float4 a1 = ((const float4*)(Arow + k0))[akq + 1];
        float4 b0 = ((const float4*)(Brow + k0))[bkq];

        As[akq*4+0][ar] = a0.x; As[akq*4+1][ar] = a0.y;
        As[akq*4+2][ar] = a0.z; As[akq*4+3][ar] = a0.w;
        As[akq*4+4][ar] = a1.x; As[akq*4+5][ar] = a1.y;
        As[akq*4+6][ar] = a1.z; As[akq*4+7][ar] = a1.w;
        Bs[bkq*4+0][br] = b0.x; Bs[bkq*4+1][br] = b0.y;
        Bs[bkq*4+2][br] = b0.z; Bs[bkq*4+3][br] = b0.w;
        __syncthreads();

        #pragma unroll
        for (int k = 0; k < BK; k++) {
            float4 av0 = ((const float4*)As[k])[ty*2];
            float4 av1 = ((const float4*)As[k])[ty*2 + 1];
            float4 bv  = ((const float4*)Bs[k])[tx];
            float am[8] = {av0.x, av0.y, av0.z, av0.w, av1.x, av1.y, av1.z, av1.w};
            float bm[4] = {bv.x, bv.y, bv.z, bv.w};
            #pragma unroll
            for (int i = 0; i < 8; i++)
                #pragma unroll
                for (int j = 0; j < 4; j++)
                    acc[i][j] += am[i] * bm[j];
        }
        __syncthreads();
    }

    #pragma unroll
    for (int i = 0; i < 8; i++) {
        int row = m0 + ty*8 + i;
        float4 o;
        if (mode == 1) {
            float4 r4 = ((const float4*)(Res + (size_t)row * N))[(n0 >> 2) + tx];
            o.x = r4.x + acc[i][0]; o.y = r4.y + acc[i][1];
            o.z = r4.z + acc[i][2]; o.w = r4.w + acc[i][3];
        } else if (mode == 2) {
            float v0 = fmaxf(acc[i][0], 0.f), v1 = fmaxf(acc[i][1], 0.f);
            float v2 = fmaxf(acc[i][2], 0.f), v3 = fmaxf(acc[i][3], 0.f);
            o.x = v0*v0; o.y = v1*v1; o.z = v2*v2; o.w = v3*v3;
        } else {
            o.x = acc[i][0]; o.y = acc[i][1]; o.z = acc[i][2]; o.w = acc[i][3];
        }
        ((float4*)(C + (size_t)row * N))[(n0 >> 2) + tx] = o;
    }
}

// ---------------- attention: 8 queries x 1 head per block, two-pass softmax ----------------
#define MQ 8
__global__ __launch_bounds__(128) void attn_kernel() {
    __shared__ float qs[MQ][HD];       // 2 KB
    __shared__ float sc[MQ][S];        // 32 KB
    __shared__ float red[MQ][2][HD];   // 4 KB
    __shared__ float s_sum[MQ];

    int h  = blockIdx.y;
    int q0 = blockIdx.x * MQ;
    int tid = threadIdx.x;

    // load 8 query vectors (512 floats = 128 float4)
    {
        int mq = tid >> 4;      // 0..7
        int c  = tid & 15;      // 0..15 float4s
        ((float4*)qs[mq])[c] = ((const float4*)(g_q + (size_t)(q0 + mq) * D + h * HD))[c];
    }
    __syncthreads();

    const float scale = 0.125f;  // HD^-0.5

    // pass 1: scores
    for (int k = tid; k < S; k += 128) {
        float4 kr[16];
        const float4* kp = (const float4*)(g_k + (size_t)k * D + h * HD);
        #pragma unroll
        for (int c = 0; c < 16; c++) kr[c] = kp[c];
        #pragma unroll
        for (int mq = 0; mq < MQ; mq++) {
            const float4* qp = (const float4*)qs[mq];
            float acc = 0.f;
            #pragma unroll
            for (int c = 0; c < 16; c++) {
                float4 qv = qp[c];
                acc += qv.x*kr[c].x + qv.y*kr[c].y + qv.z*kr[c].z + qv.w*kr[c].w;
            }
            bool ok = (g_mask[q0 + mq][k >> 5] >> (k & 31)) & 1u;
            sc[mq][k] = ok ? acc * scale : -1e30f;
        }
    }
    __syncthreads();

    // pass 2: softmax per row; warp w owns rows 2w, 2w+1 (no cross-warp sync needed)
    {
        int w = tid >> 5, lane = tid & 31;
        #pragma unroll
        for (int r = 0; r < 2; r++) {
            int mq = w * 2 + r;
            float m = -1e30f;
            for (int k = lane; k < S; k += 32) m = fmaxf(m, sc[mq][k]);
            #pragma unroll
            for (int o = 16; o > 0; o >>= 1) m = fmaxf(m, __shfl_xor_sync(0xffffffffu, m, o));
            float ssum = 0.f;
            for (int k = lane; k < S; k += 32) {
                float e = expf(sc[mq][k] - m);
                sc[mq][k] = e;
                ssum += e;
            }
            #pragma unroll
            for (int o = 16; o > 0; o >>= 1) ssum += __shfl_xor_sync(0xffffffffu, ssum, o);
            if (lane == 0) s_sum[mq] = ssum;
        }
    }
    __syncthreads();

    // pass 3: y = P @ V ; thread = (dim d, k-half)
    {
        int d = tid & 63;
        int half = tid >> 6;
        float yacc[MQ];
        #pragma unroll
        for (int mq = 0; mq < MQ; mq++) yacc[mq] = 0.f;
        int kb = half * 512;
        for (int k = kb; k < kb + 512; k += 4) {
            float v0 = g_v[(size_t)(k+0) * D + h * HD + d];
            float v1 = g_v[(size_t)(k+1) * D + h * HD + d];
            float v2 = g_v[(size_t)(k+2) * D + h * HD + d];
            float v3 = g_v[(size_t)(k+3) * D + h * HD + d];
            #pragma unroll
            for (int mq = 0; mq < MQ; mq++) {
                float4 p = ((const float4*)sc[mq])[k >> 2];
                yacc[mq] += p.x*v0 + p.y*v1 + p.z*v2 + p.w*v3;
            }
        }
        #pragma unroll
        for (int mq = 0; mq < MQ; mq++) red[mq][half][d] = yacc[mq];
        __syncthreads();
        if (half == 0) {
            #pragma unroll
            for (int mq = 0; mq < MQ; mq++) {
                float val = (red[mq][0][d] + red[mq][1][d]) / s_sum[mq];
                g_y[(size_t)(q0 + mq) * D + h * HD + d] = val;
            }
        }
    }
}

// ---------------- host orchestration ----------------
static void run_gemm(const void* A, const void* B, const void* Res, void* C,
                     int M, int N, int K, int mode) {
    dim3 grid(N / BN, M / BM);
    gemm_kernel<<<grid, 256>>>((const float*)A, (const float*)B,
                               (const float*)Res, (float*)C, M, N, K, mode);
}

extern "C" void kernel_launch(void* const* d_in, const int* in_sizes, int n_in,
                              void* d_out, int out_size) {
    const float* xin     = (const float*)d_in[0];
    const float* Wq      = (const float*)d_in[1];
    const float* Wk      = (const float*)d_in[2];
    const float* Wv      = (const float*)d_in[3];
    const float* Wo      = (const float*)d_in[4];
    const float* lamb    = (const float*)d_in[5];
    const float* lambdas = (const float*)d_in[6];
    const float* Wfc     = (const float*)d_in[7];
    const float* Wp      = (const float*)d_in[8];
    const int*   levels  = (const int*)d_in[9];
    const int*   sample  = (const int*)d_in[10];
    float* out = (float*)d_out;

    void *px, *px0, *pxl, *pxn, *pq, *pk, *pv, *py, *ph;
    cudaGetSymbolAddress(&px,  g_x);
    cudaGetSymbolAddress(&px0, g_x0);
    cudaGetSymbolAddress(&pxl, g_xl);
    cudaGetSymbolAddress(&pxn, g_xn);
    cudaGetSymbolAddress(&pq,  g_q);
    cudaGetSymbolAddress(&pk,  g_k);
    cudaGetSymbolAddress(&pv,  g_v);
    cudaGetSymbolAddress(&py,  g_y);
    cudaGetSymbolAddress(&ph,  g_h);

    const int EW_GRID = (S * D / 4) / 256;  // 1024 blocks of float4 work

    prefix_kernel<<<1, 32>>>(levels);
    mask_kernel<<<S, 32>>>(levels, sample);

    rms_kernel<<<S, 256>>>(xin, (float*)px);    // x = rms(x)
    copy_x0_kernel<<<EW_GRID, 256>>>();         // x0 = x

    for (int l = 0; l < NL; l++) {
        lerp_kernel<<<EW_GRID, 256>>>(lambdas, l);            // xl
        rms_kernel<<<S, 256>>>((const float*)pxl, (float*)pxn); // xn

        run_gemm(pxn, Wq + (size_t)l*D*D, nullptr, pq, S, D, D, 0);
        run_gemm(pxn, Wk + (size_t)l*D*D, nullptr, pk, S, D, D, 0);
        run_gemm(pxn, Wv + (size_t)l*D*D, nullptr, pv, S, D, D, 0);

        vmix_kernel<<<EW_GRID, 256>>>(lamb, l);
        qkrope_kernel<<<S, dim3(32, 16)>>>();

        attn_kernel<<<dim3(S / MQ, H), 128>>>();

        // x = xl + y @ Wo^T
        run_gemm(py, Wo + (size_t)l*D*D, pxl, px, S, D, D, 1);

        // MLP
        rms_kernel<<<S, 256>>>((const float*)px, (float*)pxn);
        run_gemm(pxn, Wfc + (size_t)l*DFF*D, nullptr, ph, S, DFF, D, 2);  // relu^2
        run_gemm(ph, Wp + (size_t)l*D*DFF, px, px, S, D, DFF, 1);         // x += h @ Wp^T
    }

    rms_kernel<<<S, 256>>>((const float*)px, out);  // final rms
}

// round 8
// speedup vs baseline: 1.3202x; 1.3202x over previous
#include <cuda_runtime.h>
#include <cuda_bf16.h>
#include <math.h>
#include <stdint.h>

#define S 1024
#define D 1024
#define H 16
#define HD 64
#define NL 6
#define DFF 4096
#define EPS 1.1920929e-07f

// ---------------- fp32 scratch ----------------
__device__ float g_x [S*D];
__device__ float g_x0[S*D];
__device__ float g_xl[S*D];
__device__ float g_xn[S*D];
__device__ float g_q [S*D];
__device__ float g_k [S*D];
__device__ float g_v [S*D];
__device__ float g_v1[S*D];
__device__ float g_y [S*D];
__device__ float g_h [S*DFF];
__device__ unsigned g_mask[S][S/32];
__device__ int g_cpad[S+1];

// ---------------- split-bf16 operand buffers (K' = 3K) ----------------
// A-side pattern: [hi | hi | lo]   B-side pattern: [hi | lo | hi]
// dot(A',B') = ah*bh + ah*bl + al*bh  (~fp32 accuracy)
__device__ __align__(256) __nv_bfloat16 g_wqkvb[(size_t)NL*3072*3072];
__device__ __align__(256) __nv_bfloat16 g_wob  [(size_t)NL*1024*3072];
__device__ __align__(256) __nv_bfloat16 g_wfcb [(size_t)NL*4096*3072];
__device__ __align__(256) __nv_bfloat16 g_wpb  [(size_t)NL*1024*12288];
__device__ __align__(256) __nv_bfloat16 g_ab   [(size_t)1024*3072];
__device__ __align__(256) __nv_bfloat16 g_hb   [(size_t)1024*12288];

__device__ __forceinline__ uint32_t smem_u32(const void* p) {
    uint32_t a;
    asm("{ .reg .u64 t; cvta.to.shared.u64 t, %1; cvt.u32.u64 %0, t; }" : "=r"(a) : "l"(p));
    return a;
}

// ================= operand conversion kernels =================
__global__ __launch_bounds__(256) void conv_kernel(const float* __restrict__ src,
                                                   __nv_bfloat16* __restrict__ dst,
                                                   int K, int aside) {
    int idx = blockIdx.x * 256 + threadIdx.x;
    int K4 = K >> 2;
    int r = idx / K4, k4 = idx - r * K4;
    float4 v = ((const float4*)src)[idx];
    __nv_bfloat16 h0 = __float2bfloat16(v.x), h1 = __float2bfloat16(v.y);
    __nv_bfloat16 h2 = __float2bfloat16(v.z), h3 = __float2bfloat16(v.w);
    __nv_bfloat16 l0 = __float2bfloat16(v.x - __bfloat162float(h0));
    __nv_bfloat16 l1 = __float2bfloat16(v.y - __bfloat162float(h1));
    __nv_bfloat16 l2 = __float2bfloat16(v.z - __bfloat162float(h2));
    __nv_bfloat16 l3 = __float2bfloat16(v.w - __bfloat162float(h3));
    size_t base = (size_t)r * 3 * K + k4 * 4;
    __nv_bfloat162 H01 = __halves2bfloat162(h0, h1), H23 = __halves2bfloat162(h2, h3);
    __nv_bfloat162 L01 = __halves2bfloat162(l0, l1), L23 = __halves2bfloat162(l2, l3);
    __nv_bfloat162* p0 = (__nv_bfloat162*)(dst + base);
    __nv_bfloat162* p1 = (__nv_bfloat162*)(dst + base + K);
    __nv_bfloat162* p2 = (__nv_bfloat162*)(dst + base + 2 * K);
    p0[0] = H01; p0[1] = H23;
    if (aside) { p1[0] = H01; p1[1] = H23; p2[0] = L01; p2[1] = L23; }
    else       { p1[0] = L01; p1[1] = L23; p2[0] = H01; p2[1] = H23; }
}

__global__ __launch_bounds__(256) void conv_qkv_kernel(const float* __restrict__ Wq,
                                                       const float* __restrict__ Wk,
                                                       const float* __restrict__ Wv) {
    int idx = blockIdx.x * 256 + threadIdx.x;
    int l = idx / (3072 * 256);
    int rem = idx - l * (3072 * 256);
    int n = rem >> 8;
    int k4 = rem & 255;
    int sel = n >> 10, nn = n & 1023;
    const float* srcm = (sel == 0) ? Wq : (sel == 1) ? Wk : Wv;
    float4 v = ((const float4*)(srcm + ((size_t)l * 1024 + nn) * 1024))[k4];
    __nv_bfloat16 h0 = __float2bfloat16(v.x), h1 = __float2bfloat16(v.y);
    __nv_bfloat16 h2 = __float2bfloat16(v.z), h3 = __float2bfloat16(v.w);
    __nv_bfloat16 l0 = __float2bfloat16(v.x - __bfloat162float(h0));
    __nv_bfloat16 l1 = __float2bfloat16(v.y - __bfloat162float(h1));
    __nv_bfloat16 l2 = __float2bfloat16(v.z - __bfloat162float(h2));
    __nv_bfloat16 l3 = __float2bfloat16(v.w - __bfloat162float(h3));
    size_t base = ((size_t)l * 3072 + n) * 3072 + k4 * 4;
    __nv_bfloat162 H01 = __halves2bfloat162(h0, h1), H23 = __halves2bfloat162(h2, h3);
    __nv_bfloat162 L01 = __halves2bfloat162(l0, l1), L23 = __halves2bfloat162(l2, l3);
    __nv_bfloat162* p0 = (__nv_bfloat162*)(g_wqkvb + base);
    __nv_bfloat162* p1 = (__nv_bfloat162*)(g_wqkvb + base + 1024);
    __nv_bfloat162* p2 = (__nv_bfloat162*)(g_wqkvb + base + 2048);
    p0[0] = H01; p0[1] = H23;
    p1[0] = L01; p1[1] = L23;   // B-side: [hi|lo|hi]
    p2[0] = H01; p2[1] = H23;
}

// ================= mma.sync bf16 GEMM: C[M,N] = A[M,Kp] * B[N,Kp]^T =================
// mode 0: C0 = acc ; 1: C0 = Res + acc ; 2: C0 = relu(acc)^2 ; 3: qkv split C0/C1/C2
// BM=128, BN=128, BK=32, 3-stage cp.async pipeline, 8 warps (2 x 4), warp tile 64x32.
#define A_PITCH 80                  // bytes per smem row: 64 data + 16 pad (bank-friendly)
#define A_STAGE (128 * A_PITCH)     // 10240 B
#define STAGE_BYTES (2 * A_STAGE)   // A + B = 20480 B
#define GSMEM_DYN (3 * STAGE_BYTES) // 61440 B

__device__ __forceinline__ void fill_stage(const __nv_bfloat16* Ab, const __nv_bfloat16* Bb,
                                           int Kp, uint32_t sA, uint32_t sB, int tid) {
    #pragma unroll
    for (int i = 0; i < 2; i++) {
        int slot = tid + i * 256;         // 0..511
        int row = slot >> 2, ch = slot & 3;
        uint32_t dst = sA + row * A_PITCH + ch * 16;
        const char* src = (const char*)(Ab + (size_t)row * Kp) + ch * 16;
        asm volatile("cp.async.cg.shared.global [%0], [%1], 16;" :: "r"(dst), "l"(src));
    }
    #pragma unroll
    for (int i = 0; i < 2; i++) {
        int slot = tid + i * 256;
        int row = slot >> 2, ch = slot & 3;
        uint32_t dst = sB + row * A_PITCH + ch * 16;
        const char* src = (const char*)(Bb + (size_t)row * Kp) + ch * 16;
        asm volatile("cp.async.cg.shared.global [%0], [%1], 16;" :: "r"(dst), "l"(src));
    }
}

__global__ __launch_bounds__(256) void tc_gemm(
    const __nv_bfloat16* __restrict__ A, const __nv_bfloat16* __restrict__ B,
    const float* __restrict__ Res, float* __restrict__ C0,
    float* __restrict__ C1, float* __restrict__ C2,
    int M, int N, int Kp, int mode)
{
    extern __shared__ __align__(128) char dyn[];
    const int tid = threadIdx.x;
    const int wid = tid >> 5;
    const int lane = tid & 31;
    const int warp_m = wid >> 2;        // 0..1 (64 rows each)
    const int warp_n = wid & 3;         // 0..3 (32 cols each)
    const uint32_t sb0 = smem_u32(dyn);

    const int m0 = blockIdx.y * 128, n0 = blockIdx.x * 128;
    const int NC = Kp >> 5;             // chunks of K=32
    const __nv_bfloat16* Abase = A + (size_t)m0 * Kp;
    const __nv_bfloat16* Bbase = B + (size_t)n0 * Kp;

    float acc[4][4][4];
    #pragma unroll
    for (int mt = 0; mt < 4; mt++)
        #pragma unroll
        for (int nt = 0; nt < 4; nt++)
            #pragma unroll
            for (int r = 0; r < 4; r++) acc[mt][nt][r] = 0.f;

    // prologue: fill 3 stages
    #pragma unroll
    for (int s = 0; s < 3; s++) {
        fill_stage(Abase + s * 32, Bbase + s * 32, Kp,
                   sb0 + s * STAGE_BYTES, sb0 + s * STAGE_BYTES + A_STAGE, tid);
        asm volatile("cp.async.commit_group;" ::: "memory");
    }

    // per-lane ldmatrix addresses (within-tile components)
    const int a_row = lane & 15;            // m row within 16
    const int a_kc  = (lane >> 4) * 16;     // k-chunk byte offset (0 or 16)
    const int b_row = ((lane & 16) >> 1) + (lane & 7);   // 0-7 or 8-15 (n within 16)
    const int b_kc  = ((lane >> 3) & 1) * 16;

    for (int c = 0; c < NC; c++) {
        int st = c % 3;
        asm volatile("cp.async.wait_group 2;" ::: "memory");
        __syncthreads();

        uint32_t sA = sb0 + st * STAGE_BYTES;
        uint32_t sB = sA + A_STAGE;

        #pragma unroll
        for (int ks = 0; ks < 2; ks++) {
            uint32_t a[4][4];
            #pragma unroll
            for (int mt = 0; mt < 4; mt++) {
                uint32_t addr = sA + (warp_m * 64 + mt * 16 + a_row) * A_PITCH + ks * 32 + a_kc;
                asm volatile("ldmatrix.sync.aligned.m8n8.x4.shared.b16 {%0,%1,%2,%3}, [%4];"
                    : "=r"(a[mt][0]), "=r"(a[mt][1]), "=r"(a[mt][2]), "=r"(a[mt][3]) : "r"(addr));
            }
            uint32_t b[4][2];
            #pragma unroll
            for (int nt2 = 0; nt2 < 2; nt2++) {
                uint32_t addr = sB + (warp_n * 32 + nt2 * 16 + b_row) * A_PITCH + ks * 32 + b_kc;
                asm volatile("ldmatrix.sync.aligned.m8n8.x4.shared.b16 {%0,%1,%2,%3}, [%4];"
                    : "=r"(b[nt2*2][0]), "=r"(b[nt2*2][1]), "=r"(b[nt2*2+1][0]), "=r"(b[nt2*2+1][1])
                    : "r"(addr));
            }
            #pragma unroll
            for (int mt = 0; mt < 4; mt++)
                #pragma unroll
                for (int nt = 0; nt < 4; nt++)
                    asm volatile(
                        "mma.sync.aligned.m16n8k16.row.col.f32.bf16.bf16.f32 "
                        "{%0,%1,%2,%3}, {%4,%5,%6,%7}, {%8,%9}, {%0,%1,%2,%3};"
                        : "+f"(acc[mt][nt][0]), "+f"(acc[mt][nt][1]),
                          "+f"(acc[mt][nt][2]), "+f"(acc[mt][nt][3])
                        : "r"(a[mt][0]), "r"(a[mt][1]), "r"(a[mt][2]), "r"(a[mt][3]),
                          "r"(b[nt][0]), "r"(b[nt][1]));
        }
        __syncthreads();
        if (c + 3 < NC)
            fill_stage(Abase + (c + 3) * 32, Bbase + (c + 3) * 32, Kp,
                       sb0 + st * STAGE_BYTES, sb0 + st * STAGE_BYTES + A_STAGE, tid);
        asm volatile("cp.async.commit_group;" ::: "memory");
    }

    // epilogue: fragments -> gmem (float2 stores)
    const int qrow = lane >> 2;
    const int qcol = (lane & 3) * 2;
    #pragma unroll
    for (int mt = 0; mt < 4; mt++) {
        #pragma unroll
        for (int nt = 0; nt < 4; nt++) {
            int gr = m0 + warp_m * 64 + mt * 16 + qrow;
            int gc = n0 + warp_n * 32 + nt * 8 + qcol;
            #pragma unroll
            for (int half = 0; half < 2; half++) {
                int row = gr + half * 8;
                float2 v = make_float2(acc[mt][nt][half*2], acc[mt][nt][half*2+1]);
                if (mode == 1) {
                    float2 rr = *(const float2*)(Res + (size_t)row * N + gc);
                    v.x += rr.x; v.y += rr.y;
                } else if (mode == 2) {
                    float a0 = fmaxf(v.x, 0.f), a1 = fmaxf(v.y, 0.f);
                    v.x = a0 * a0; v.y = a1 * a1;
                }
                if (mode == 3) {
                    int sel = gc >> 10;
                    float* Cd = (sel == 0) ? C0 : (sel == 1) ? C1 : C2;
                    *(float2*)(Cd + (size_t)row * 1024 + (gc & 1023)) = v;
                } else {
                    *(float2*)(C0 + (size_t)row * N + gc) = v;
                }
            }
        }
    }
}

// ================= mask / norm / elementwise / attention =================
__global__ void prefix_kernel(const int* __restrict__ levels) {
    if (blockIdx.x == 0 && threadIdx.x == 0) {
        int c = 0;
        g_cpad[0] = 0;
        for (int i = 0; i < S; i++) { c += (levels[i] == 0); g_cpad[i+1] = c; }
    }
}

__global__ void mask_kernel(const int* __restrict__ levels, const int* __restrict__ sidx) {
    int q = blockIdx.x;
    int w = threadIdx.x;
    int sq = sidx[q];
    int cq = g_cpad[q];
    unsigned bits = 0u;
    #pragma unroll
    for (int j = 0; j < 32; j++) {
        int k = w * 32 + j;
        bool ok = (k <= q) && (sidx[k] == sq);
        if (ok && (levels[k] == 0) && (cq - g_cpad[k+1] > 0)) ok = false;
        if (ok) bits |= (1u << j);
    }
    g_mask[q][w] = bits;
}

__global__ __launch_bounds__(256) void rms_kernel(const float* __restrict__ in,
                                                  float* __restrict__ out) {
    __shared__ float sred[8];
    int row = blockIdx.x;
    const float4* ip = (const float4*)(in + (size_t)row * D);
    float4* op = (float4*)(out + (size_t)row * D);
    float4 a = ip[threadIdx.x];
    float s = a.x*a.x + a.y*a.y + a.z*a.z + a.w*a.w;
    #pragma unroll
    for (int o = 16; o > 0; o >>= 1) s += __shfl_xor_sync(0xffffffffu, s, o);
    if ((threadIdx.x & 31) == 0) sred[threadIdx.x >> 5] = s;
    __syncthreads();
    if (threadIdx.x == 0) {
        float t = 0.f;
        #pragma unroll
        for (int i = 0; i < 8; i++) t += sred[i];
        sred[0] = t;
    }
    __syncthreads();
    float r = rsqrtf(sred[0] * (1.0f / (float)D) + EPS);
    a.x *= r; a.y *= r; a.z *= r; a.w *= r;
    op[threadIdx.x] = a;
}

__global__ void copy_x0_kernel() {
    int i = blockIdx.x * 256 + threadIdx.x;
    ((float4*)g_x0)[i] = ((const float4*)g_x)[i];
}

__global__ void lerp_kernel(const float* __restrict__ lambdas, int layer) {
    float l0 = lambdas[layer*2 + 0];
    float l1 = lambdas[layer*2 + 1];
    int i = blockIdx.x * 256 + threadIdx.x;
    float4 a = ((const float4*)g_x )[i];
    float4 b = ((const float4*)g_x0)[i];
    float4 o;
    o.x = l0*a.x + l1*b.x; o.y = l0*a.y + l1*b.y;
    o.z = l0*a.z + l1*b.z; o.w = l0*a.w + l1*b.w;
    ((float4*)g_xl)[i] = o;
}

__global__ void vmix_kernel(const float* __restrict__ lamb, int layer) {
    int i = blockIdx.x * 256 + threadIdx.x;
    if (layer == 0) {
        ((float4*)g_v1)[i] = ((const float4*)g_v)[i];
    } else {
        float l = lamb[layer];
        float4 v = ((const float4*)g_v )[i];
        float4 u = ((const float4*)g_v1)[i];
        float4 o;
        o.x = (1.f-l)*v.x + l*u.x; o.y = (1.f-l)*v.y + l*u.y;
        o.z = (1.f-l)*v.z + l*u.z; o.w = (1.f-l)*v.w + l*u.w;
        ((float4*)g_v)[i] = o;
    }
}

__global__ __launch_bounds__(512) void qkrope_kernel() {
    int t = blockIdx.x;
    int h = threadIdx.y;
    int j = threadIdx.x;
    float inv = powf(10000.f, -(float)j / 32.f);
    float fr = (float)t * inv;
    float c = cosf(fr), sn = sinf(fr);
    #pragma unroll
    for (int which = 0; which < 2; which++) {
        float* p = (which ? g_k : g_q) + (size_t)t * D + h * HD;
        float a = p[j];
        float b = p[j + 32];
        float ss = a*a + b*b;
        #pragma unroll
        for (int o = 16; o > 0; o >>= 1) ss += __shfl_xor_sync(0xffffffffu, ss, o);
        float r = rsqrtf(ss * (1.0f/64.0f) + EPS);
        a *= r; b *= r;
        p[j]      =  a*c + b*sn;
        p[j + 32] = -a*sn + b*c;
    }
}

#define MQ 8
__global__ __launch_bounds__(128) void attn_kernel() {
    __shared__ float qs[MQ][HD];
    __shared__ float sc[MQ][S];
    __shared__ float red[MQ][2][HD];
    __shared__ float s_sum[MQ];

    int h  = blockIdx.y;
    int q0 = blockIdx.x * MQ;
    int tid = threadIdx.x;

    {
        int mq = tid >> 4;
        int c  = tid & 15;
        ((float4*)qs[mq])[c] = ((const float4*)(g_q + (size_t)(q0 + mq) * D + h * HD))[c];
    }
    __syncthreads();

    const float scale = 0.125f;

    for (int k = tid; k < S; k += 128) {
        float4 kr[16];
        const float4* kp = (const float4*)(g_k + (size_t)k * D + h * HD);
        #pragma unroll
        for (int c = 0; c < 16; c++) kr[c] = kp[c];
        #pragma unroll
        for (int mq = 0; mq < MQ; mq++) {
            const float4* qp = (const float4*)qs[mq];
            float acc = 0.f;
            #pragma unroll
            for (int c = 0; c < 16; c++) {
                float4 qv = qp[c];
                acc += qv.x*kr[c].x + qv.y*kr[c].y + qv.z*kr[c].z + qv.w*kr[c].w;
            }
            bool ok = (g_mask[q0 + mq][k >> 5] >> (k & 31)) & 1u;
            sc[mq][k] = ok ? acc * scale : -1e30f;
        }
    }
    __syncthreads();

    {
        int w = tid >> 5, lane = tid & 31;
        #pragma unroll
        for (int r = 0; r < 2; r++) {
            int mq = w * 2 + r;
            float m = -1e30f;
            for (int k = lane; k < S; k += 32) m = fmaxf(m, sc[mq][k]);
            #pragma unroll
            for (int o = 16; o > 0; o >>= 1) m = fmaxf(m, __shfl_xor_sync(0xffffffffu, m, o));
            float ssum = 0.f;
            for (int k = lane; k < S; k += 32) {
                float e = expf(sc[mq][k] - m);
                sc[mq][k] = e;
                ssum += e;
            }
            #pragma unroll
            for (int o = 16; o > 0; o >>= 1) ssum += __shfl_xor_sync(0xffffffffu, ssum, o);
            if (lane == 0) s_sum[mq] = ssum;
        }
    }
    __syncthreads();

    {
        int d = tid & 63;
        int half = tid >> 6;
        float yacc[MQ];
        #pragma unroll
        for (int mq = 0; mq < MQ; mq++) yacc[mq] = 0.f;
        int kb = half * 512;
        for (int k = kb; k < kb + 512; k += 4) {
            float v0 = g_v[(size_t)(k+0) * D + h * HD + d];
            float v1 = g_v[(size_t)(k+1) * D + h * HD + d];
            float v2 = g_v[(size_t)(k+2) * D + h * HD + d];
            float v3 = g_v[(size_t)(k+3) * D + h * HD + d];
            #pragma unroll
            for (int mq = 0; mq < MQ; mq++) {
                float4 p = ((const float4*)sc[mq])[k >> 2];
                yacc[mq] += p.x*v0 + p.y*v1 + p.z*v2 + p.w*v3;
            }
        }
        #pragma unroll
        for (int mq = 0; mq < MQ; mq++) red[mq][half][d] = yacc[mq];
        __syncthreads();
        if (half == 0) {
            #pragma unroll
            for (int mq = 0; mq < MQ; mq++) {
                float val = (red[mq][0][d] + red[mq][1][d]) / s_sum[mq];
                g_y[(size_t)(q0 + mq) * D + h * HD + d] = val;
            }
        }
    }
}

// ================= host orchestration =================
extern "C" void kernel_launch(void* const* d_in, const int* in_sizes, int n_in,
                              void* d_out, int out_size) {
    const float* xin     = (const float*)d_in[0];
    const float* Wq      = (const float*)d_in[1];
    const float* Wk      = (const float*)d_in[2];
    const float* Wv      = (const float*)d_in[3];
    const float* Wo      = (const float*)d_in[4];
    const float* lamb    = (const float*)d_in[5];
    const float* lambdas = (const float*)d_in[6];
    const float* Wfc     = (const float*)d_in[7];
    const float* Wp      = (const float*)d_in[8];
    const int*   levels  = (const int*)d_in[9];
    const int*   sample  = (const int*)d_in[10];
    float* out = (float*)d_out;

    cudaFuncSetAttribute(tc_gemm, cudaFuncAttributeMaxDynamicSharedMemorySize, GSMEM_DYN);

    void *px, *pxl, *pxn, *pq, *pk, *pv, *py, *ph;
    void *pwqkvb, *pwob, *pwfcb, *pwpb, *pab, *phb;
    cudaGetSymbolAddress(&px,  g_x);
    cudaGetSymbolAddress(&pxl, g_xl);
    cudaGetSymbolAddress(&pxn, g_xn);
    cudaGetSymbolAddress(&pq,  g_q);
    cudaGetSymbolAddress(&pk,  g_k);
    cudaGetSymbolAddress(&pv,  g_v);
    cudaGetSymbolAddress(&py,  g_y);
    cudaGetSymbolAddress(&ph,  g_h);
    cudaGetSymbolAddress(&pwqkvb, g_wqkvb);
    cudaGetSymbolAddress(&pwob,   g_wob);
    cudaGetSymbolAddress(&pwfcb,  g_wfcb);
    cudaGetSymbolAddress(&pwpb,   g_wpb);
    cudaGetSymbolAddress(&pab,    g_ab);
    cudaGetSymbolAddress(&phb,    g_hb);

    const int EW_GRID = (S * D / 4) / 256;

    // weight conversions (every launch; deterministic)
    conv_qkv_kernel<<<NL * 3072 * 256 / 256, 256>>>(Wq, Wk, Wv);
    conv_kernel<<<(NL * 1024 * 1024 / 4) / 256, 256>>>(Wo,  (__nv_bfloat16*)pwob,  1024, 0);
    conv_kernel<<<(NL * 4096 * 1024 / 4) / 256, 256>>>(Wfc, (__nv_bfloat16*)pwfcb, 1024, 0);
    conv_kernel<<<(NL * 1024 * 4096 / 4) / 256, 256>>>(Wp,  (__nv_bfloat16*)pwpb,  4096, 0);

    prefix_kernel<<<1, 32>>>(levels);
    mask_kernel<<<S, 32>>>(levels, sample);

    rms_kernel<<<S, 256>>>(xin, (float*)px);
    copy_x0_kernel<<<EW_GRID, 256>>>();

    for (int l = 0; l < NL; l++) {
        lerp_kernel<<<EW_GRID, 256>>>(lambdas, l);
        rms_kernel<<<S, 256>>>((const float*)pxl, (float*)pxn);

        // fused QKV GEMM (bf16 split, tensor cores), epilogue splits columns
        conv_kernel<<<(S * D / 4) / 256, 256>>>((const float*)pxn, (__nv_bfloat16*)pab, 1024, 1);
        tc_gemm<<<dim3(3072/128, S/128), 256, GSMEM_DYN>>>(
            (const __nv_bfloat16*)pab, (const __nv_bfloat16*)pwqkvb + (size_t)l*3072*3072,
            nullptr, (float*)pq, (float*)pk, (float*)pv, S, 3072, 3072, 3);

        vmix_kernel<<<EW_GRID, 256>>>(lamb, l);
        qkrope_kernel<<<S, dim3(32, 16)>>>();
        attn_kernel<<<dim3(S / MQ, H), 128>>>();

        // x = xl + y @ Wo^T
        conv_kernel<<<(S * D / 4) / 256, 256>>>((const float*)py, (__nv_bfloat16*)pab, 1024, 1);
        tc_gemm<<<dim3(1024/128, S/128), 256, GSMEM_DYN>>>(
            (const __nv_bfloat16*)pab, (const __nv_bfloat16*)pwob + (size_t)l*1024*3072,
            (const float*)pxl, (float*)px, nullptr, nullptr, S, 1024, 3072, 1);

        // MLP
        rms_kernel<<<S, 256>>>((const float*)px, (float*)pxn);
        conv_kernel<<<(S * D / 4) / 256, 256>>>((const float*)pxn, (__nv_bfloat16*)pab, 1024, 1);
        tc_gemm<<<dim3(4096/128, S/128), 256, GSMEM_DYN>>>(
            (const __nv_bfloat16*)pab, (const __nv_bfloat16*)pwfcb + (size_t)l*4096*3072,
            nullptr, (float*)ph, nullptr, nullptr, S, 4096, 3072, 2);

        conv_kernel<<<(S * DFF / 4) / 256, 256>>>((const float*)ph, (__nv_bfloat16*)phb, 4096, 1);
        tc_gemm<<<dim3(1024/128, S/128), 256, GSMEM_DYN>>>(
            (const __nv_bfloat16*)phb, (const __nv_bfloat16*)pwpb + (size_t)l*1024*12288,
            (const float*)px, (float*)px, nullptr, nullptr, S, 1024, 12288, 1);
    }

    rms_kernel<<<S, 256>>>((const float*)px, out);
}